// round 9
// baseline (speedup 1.0000x reference)
#include <cuda_runtime.h>
#include <mma.h>
#include <math.h>

using namespace nvcuda;

#define LL 2048
#define DD 2048
#define NH 32
#define NKV 8
#define HDIM 64
#define QKVN 3072

__device__ float g_qkv[LL * QKVN];
__device__ float g_attn[LL * DD];
// tf32-purified copies of inputs
__device__ float g_x [LL * DD];
__device__ float g_wq[DD * 2048];
__device__ float g_wk[DD * 512];
__device__ float g_wv[DD * 512];
__device__ float g_wo[DD * DD];

// ---------------------------------------------------------------------------
// cp.async helpers
// ---------------------------------------------------------------------------
__device__ __forceinline__ void cp_async16(void* smem, const void* gmem) {
    unsigned saddr = (unsigned)__cvta_generic_to_shared(smem);
    asm volatile("cp.async.cg.shared.global [%0], [%1], 16;\n" :: "r"(saddr), "l"(gmem));
}
__device__ __forceinline__ void cp_commit() {
    asm volatile("cp.async.commit_group;\n");
}
template <int N>
__device__ __forceinline__ void cp_wait() {
    asm volatile("cp.async.wait_group %0;\n" :: "n"(N));
}

// ---------------------------------------------------------------------------
// tf32 purify prepass: dst[i] = tf32_round(src[i])
// ---------------------------------------------------------------------------
__global__ void purify_kernel(const float* __restrict__ src, float* __restrict__ dst, int n4)
{
    int i = blockIdx.x * blockDim.x + threadIdx.x;
    int stride = gridDim.x * blockDim.x;
    for (; i < n4; i += stride) {
        float4 v = ((const float4*)src)[i];
        v.x = wmma::__float_to_tf32(v.x);
        v.y = wmma::__float_to_tf32(v.y);
        v.z = wmma::__float_to_tf32(v.z);
        v.w = wmma::__float_to_tf32(v.w);
        ((float4*)dst)[i] = v;
    }
}

// ---------------------------------------------------------------------------
// WMMA typedefs (tf32, m16n16k8)
// ---------------------------------------------------------------------------
typedef wmma::fragment<wmma::matrix_a, 16, 16, 8, wmma::precision::tf32, wmma::row_major> AFrag;
typedef wmma::fragment<wmma::matrix_b, 16, 16, 8, wmma::precision::tf32, wmma::row_major> BFrag;
typedef wmma::fragment<wmma::matrix_b, 16, 16, 8, wmma::precision::tf32, wmma::col_major> BFragT;
typedef wmma::fragment<wmma::accumulator, 16, 16, 8, float> CFrag;

__device__ __forceinline__ void frag_to_tf32(float* x, int n) {
#pragma unroll
    for (int t = 0; t < n; t++) x[t] = wmma::__float_to_tf32(x[t]);
}

// ---------------------------------------------------------------------------
// Double-buffered tf32 GEMM: 128x128 tile, KC=32, 256 threads, 8 warps (32x64)
// Inputs must be tf32-valued already (no per-fragment cvt).
// ---------------------------------------------------------------------------
#define KC 32
#define A_LD 40
#define B_LD 136
#define GEMM_SMEM ((2 * 128 * A_LD + 2 * KC * B_LD) * 4)  // 75,776 B

template <bool ROUND_OUT>
__device__ __forceinline__ void gemm_pipe(
    const float* __restrict__ A, const float* __restrict__ Bp, int ldb, int cb,
    float* __restrict__ C, int ldc, int r0, int c0)
{
    extern __shared__ float sh[];
    float* As = sh;
    float* Bs = sh + 2 * 128 * A_LD;

    const int tid = threadIdx.x;
    const int w = tid >> 5;
    const int wm = w & 3;
    const int wn = w >> 2;

    CFrag acc[2][4];
#pragma unroll
    for (int i = 0; i < 2; i++)
#pragma unroll
        for (int j = 0; j < 4; j++) wmma::fill_fragment(acc[i][j], 0.f);

#define G_LOAD_STAGE(s, k0)                                                         \
    do {                                                                            \
        _Pragma("unroll") for (int it = 0; it < 4; it++) {                          \
            int lin = tid + it * 256;                                               \
            int row = lin >> 3;                                                     \
            int c4 = (lin & 7) * 4;                                                 \
            cp_async16(&As[(s) * 128 * A_LD + row * A_LD + c4],                     \
                       A + (size_t)(r0 + row) * DD + (k0) + c4);                    \
        }                                                                           \
        _Pragma("unroll") for (int it = 0; it < 4; it++) {                          \
            int lin = tid + it * 256;                                               \
            int row = lin >> 5;                                                     \
            int c4 = (lin & 31) * 4;                                                \
            cp_async16(&Bs[(s) * KC * B_LD + row * B_LD + c4],                      \
                       Bp + (size_t)((k0) + row) * ldb + cb + c4);                  \
        }                                                                           \
    } while (0)

    G_LOAD_STAGE(0, 0);
    cp_commit();

    int s = 0;
    for (int k0 = 0; k0 < DD; k0 += KC, s ^= 1) {
        if (k0 + KC < DD) G_LOAD_STAGE(s ^ 1, k0 + KC);
        cp_commit();
        cp_wait<1>();
        __syncthreads();

        const float* Ab = &As[s * 128 * A_LD];
        const float* Bb = &Bs[s * KC * B_LD];
#pragma unroll
        for (int ks = 0; ks < 4; ks++) {
            AFrag a[2];
            BFrag b[4];
#pragma unroll
            for (int i = 0; i < 2; i++)
                wmma::load_matrix_sync(a[i], Ab + (wm * 32 + i * 16) * A_LD + ks * 8, A_LD);
#pragma unroll
            for (int j = 0; j < 4; j++)
                wmma::load_matrix_sync(b[j], Bb + (ks * 8) * B_LD + wn * 64 + j * 16, B_LD);
#pragma unroll
            for (int i = 0; i < 2; i++)
#pragma unroll
                for (int j = 0; j < 4; j++)
                    wmma::mma_sync(acc[i][j], a[i], b[j], acc[i][j]);
        }
        __syncthreads();
    }

#pragma unroll
    for (int i = 0; i < 2; i++)
#pragma unroll
        for (int j = 0; j < 4; j++) {
            if (ROUND_OUT) frag_to_tf32(acc[i][j].x, acc[i][j].num_elements);
            wmma::store_matrix_sync(
                C + (size_t)(r0 + wm * 32 + i * 16) * ldc + c0 + wn * 64 + j * 16,
                acc[i][j], ldc, wmma::mem_row_major);
        }
#undef G_LOAD_STAGE
}

__global__ __launch_bounds__(256, 2) void gemm_qkv_kernel()
{
    const int r0 = blockIdx.y * 128;
    const int c0 = blockIdx.x * 128;
    const float* Bp; int ldb; int cb;
    if (c0 < 2048)      { Bp = g_wq; ldb = 2048; cb = c0; }
    else if (c0 < 2560) { Bp = g_wk; ldb = 512;  cb = c0 - 2048; }
    else                { Bp = g_wv; ldb = 512;  cb = c0 - 2560; }
    gemm_pipe<true>(g_x, Bp, ldb, cb, g_qkv, QKVN, r0, c0);
}

__global__ __launch_bounds__(256, 2) void gemm_out_kernel(float* __restrict__ outp)
{
    gemm_pipe<false>(g_attn, g_wo, DD, blockIdx.x * 128, outp, DD,
                     blockIdx.y * 128, blockIdx.x * 128);
}

// ---------------------------------------------------------------------------
// RoPE (in-place, outputs rounded to tf32)
// ---------------------------------------------------------------------------
__global__ void rope_kernel(const float* __restrict__ fc, const float* __restrict__ fs)
{
    int idx = blockIdx.x * blockDim.x + threadIdx.x;
    const int total = LL * (NH + NKV) * (HDIM / 2);
    if (idx >= total) return;
    int i    = idx & 31;
    int rem  = idx >> 5;
    int head = rem % (NH + NKV);
    int l    = rem / (NH + NKV);
    int col  = (head < NH) ? head * HDIM + 2 * i
                           : 2048 + (head - NH) * HDIM + 2 * i;
    float* p = g_qkv + (size_t)l * QKVN + col;
    float xr = p[0], xi = p[1];
    float c = fc[l * 32 + i], s = fs[l * 32 + i];
    p[0] = wmma::__float_to_tf32(xr * c - xi * s);
    p[1] = wmma::__float_to_tf32(xr * s + xi * c);
}

// ---------------------------------------------------------------------------
// Flash attention: 128-row Q tile x 64-col K tiles, 512 threads (16 warps),
// tf32 WMMA (inputs tf32-valued; only P fragments need cvt),
// double-buffered cp.async K/V.
// ---------------------------------------------------------------------------
#define T_LD 72
#define ATT_SMEM ((3 * 128 * T_LD + 4 * 64 * T_LD + 2 * 128) * 4)

__global__ __launch_bounds__(512) void attn_kernel()
{
    const int h   = blockIdx.x;
    const int qt  = (gridDim.y - 1) - blockIdx.y;   // big tiles first
    const int kvh = h >> 2;

    extern __shared__ float sm[];
    float* Qs = sm;                      // [128][T_LD] (pre-scaled)
    float* Ss = Qs + 128 * T_LD;         // [128][T_LD]
    float* Os = Ss + 128 * T_LD;         // [128][T_LD]
    float* Ks = Os + 128 * T_LD;         // [2][64][T_LD]
    float* Vs = Ks + 2 * 64 * T_LD;      // [2][64][T_LD]
    float* m_s = Vs + 2 * 64 * T_LD;     // [128]
    float* l_s = m_s + 128;

    const int tid = threadIdx.x;
    const int w  = tid >> 5;
    const int wm = w & 7;        // 16-row slab
    const int wn = w >> 3;       // 32-col slab
    const int qrow = tid >> 2;   // 0..127
    const int part = tid & 3;

#define A_LOAD_KV(s, kt)                                                            \
    do {                                                                            \
        const float* base0 = g_qkv + (size_t)((kt) * 64) * QKVN;                    \
        _Pragma("unroll") for (int it = 0; it < 2; it++) {                          \
            int lin = tid + it * 512;                                               \
            int row = lin >> 4;                                                     \
            int c4 = (lin & 15) * 4;                                                \
            const float* rb = base0 + (size_t)row * QKVN;                           \
            cp_async16(&Ks[(s) * 64 * T_LD + row * T_LD + c4],                      \
                       rb + 2048 + kvh * HDIM + c4);                                \
            cp_async16(&Vs[(s) * 64 * T_LD + row * T_LD + c4],                      \
                       rb + 2560 + kvh * HDIM + c4);                                \
        }                                                                           \
    } while (0)

    A_LOAD_KV(0, 0);
    cp_commit();

    // load Q (scaled by 1/8 — exact power of two keeps tf32-ness)
#pragma unroll
    for (int it = 0; it < 4; it++) {
        int lin = tid + it * 512;
        int row = lin >> 4;
        int c4  = (lin & 15) * 4;
        float4 v = *(const float4*)(g_qkv + (size_t)(qt * 128 + row) * QKVN + h * HDIM + c4);
        *(float4*)(&Qs[row * T_LD + c4]) =
            make_float4(v.x * 0.125f, v.y * 0.125f, v.z * 0.125f, v.w * 0.125f);
    }
    // zero O
#pragma unroll
    for (int it = 0; it < 16; it++) {
        int lin = tid + it * 512;
        Os[(lin >> 6) * T_LD + (lin & 63)] = 0.f;
    }
    if (tid < 128) { m_s[tid] = -1e30f; l_s[tid] = 0.f; }

    const int nkt = 2 * qt + 2;
    int s = 0;
    for (int kt = 0; kt < nkt; kt++, s ^= 1) {
        if (kt + 1 < nkt) A_LOAD_KV(s ^ 1, kt + 1);
        cp_commit();
        cp_wait<1>();
        __syncthreads();

        const float* Kb = &Ks[s * 64 * T_LD];
        const float* Vb = &Vs[s * 64 * T_LD];

        // S = Qs @ K^T   (Q, K already tf32-valued)
        {
            CFrag sacc[2];
            wmma::fill_fragment(sacc[0], 0.f);
            wmma::fill_fragment(sacc[1], 0.f);
#pragma unroll
            for (int ks = 0; ks < 8; ks++) {
                AFrag a;
                wmma::load_matrix_sync(a, &Qs[(wm * 16) * T_LD + ks * 8], T_LD);
#pragma unroll
                for (int j = 0; j < 2; j++) {
                    BFragT b;
                    wmma::load_matrix_sync(b, Kb + (wn * 32 + j * 16) * T_LD + ks * 8, T_LD);
                    wmma::mma_sync(sacc[j], a, b, sacc[j]);
                }
            }
#pragma unroll
            for (int j = 0; j < 2; j++)
                wmma::store_matrix_sync(&Ss[(wm * 16) * T_LD + wn * 32 + j * 16],
                                        sacc[j], T_LD, wmma::mem_row_major);
        }
        __syncthreads();

        // online softmax + O rescale: quad of 4 threads per row, 16 cols each
        {
            const bool tail = (kt >= 2 * qt);
            const int qi = qt * 128 + qrow;
            float vals[16];
            float pm = -1e30f;
#pragma unroll
            for (int kk = 0; kk < 16; kk++) {
                float v = Ss[qrow * T_LD + part * 16 + kk];
                if (tail && (kt * 64 + part * 16 + kk > qi)) v = -1e30f;
                vals[kk] = v;
                pm = fmaxf(pm, v);
            }
            pm = fmaxf(pm, __shfl_xor_sync(0xffffffffu, pm, 1));
            pm = fmaxf(pm, __shfl_xor_sync(0xffffffffu, pm, 2));
            float m_old = m_s[qrow];
            float m_new = fmaxf(m_old, pm);
            float ps = 0.f;
#pragma unroll
            for (int kk = 0; kk < 16; kk++) {
                float e = __expf(vals[kk] - m_new);
                Ss[qrow * T_LD + part * 16 + kk] = e;
                ps += e;
            }
            ps += __shfl_xor_sync(0xffffffffu, ps, 1);
            ps += __shfl_xor_sync(0xffffffffu, ps, 2);
            float alpha = __expf(m_old - m_new);
#pragma unroll
            for (int kk = 0; kk < 16; kk++)
                Os[qrow * T_LD + part * 16 + kk] *= alpha;
            if (part == 0) {
                l_s[qrow] = l_s[qrow] * alpha + ps;
                m_s[qrow] = m_new;
            }
        }
        __syncthreads();

        // O += P @ V   (P needs cvt; V already tf32-valued)
        {
#pragma unroll
            for (int j = 0; j < 2; j++) {
                CFrag oacc;
                wmma::load_matrix_sync(oacc, &Os[(wm * 16) * T_LD + wn * 32 + j * 16],
                                       T_LD, wmma::mem_row_major);
#pragma unroll
                for (int ks = 0; ks < 8; ks++) {
                    AFrag a;
                    wmma::load_matrix_sync(a, &Ss[(wm * 16) * T_LD + ks * 8], T_LD);
                    frag_to_tf32(a.x, a.num_elements);
                    BFrag b;
                    wmma::load_matrix_sync(b, Vb + (ks * 8) * T_LD + wn * 32 + j * 16, T_LD);
                    wmma::mma_sync(oacc, a, b, oacc);
                }
                wmma::store_matrix_sync(&Os[(wm * 16) * T_LD + wn * 32 + j * 16],
                                        oacc, T_LD, wmma::mem_row_major);
            }
        }
        __syncthreads();
    }

    // final normalize + write (rounded to tf32 for gemm_out)
#pragma unroll
    for (int it = 0; it < 16; it++) {
        int lin = tid + it * 512;
        int row = lin >> 6;
        int col = lin & 63;
        g_attn[(size_t)(qt * 128 + row) * DD + h * HDIM + col] =
            wmma::__float_to_tf32(Os[row * T_LD + col] / l_s[row]);
    }
#undef A_LOAD_KV
}

// ---------------------------------------------------------------------------
extern "C" void kernel_launch(void* const* d_in, const int* in_sizes, int n_in,
                              void* d_out, int out_size)
{
    const float* x  = (const float*)d_in[0];
    const float* wq = (const float*)d_in[1];
    const float* wk = (const float*)d_in[2];
    const float* wv = (const float*)d_in[3];
    const float* wo = (const float*)d_in[4];
    const float* fc = (const float*)d_in[5];
    const float* fs = (const float*)d_in[6];
    float* outp = (float*)d_out;

    cudaFuncSetAttribute(gemm_qkv_kernel, cudaFuncAttributeMaxDynamicSharedMemorySize, GEMM_SMEM);
    cudaFuncSetAttribute(gemm_out_kernel, cudaFuncAttributeMaxDynamicSharedMemorySize, GEMM_SMEM);
    cudaFuncSetAttribute(attn_kernel, cudaFuncAttributeMaxDynamicSharedMemorySize, ATT_SMEM);

    float* pg_x;  cudaGetSymbolAddress((void**)&pg_x,  g_x);
    float* pg_wq; cudaGetSymbolAddress((void**)&pg_wq, g_wq);
    float* pg_wk; cudaGetSymbolAddress((void**)&pg_wk, g_wk);
    float* pg_wv; cudaGetSymbolAddress((void**)&pg_wv, g_wv);
    float* pg_wo; cudaGetSymbolAddress((void**)&pg_wo, g_wo);

    purify_kernel<<<1184, 256>>>(x,  pg_x,  LL * DD / 4);
    purify_kernel<<<1184, 256>>>(wq, pg_wq, DD * 2048 / 4);
    purify_kernel<<<592,  256>>>(wk, pg_wk, DD * 512 / 4);
    purify_kernel<<<592,  256>>>(wv, pg_wv, DD * 512 / 4);
    purify_kernel<<<1184, 256>>>(wo, pg_wo, DD * DD / 4);

    gemm_qkv_kernel<<<dim3(24, 16), 256, GEMM_SMEM>>>();

    int total = LL * (NH + NKV) * (HDIM / 2);
    rope_kernel<<<(total + 255) / 256, 256>>>(fc, fs);

    attn_kernel<<<dim3(32, 16), 512, ATT_SMEM>>>();

    gemm_out_kernel<<<dim3(16, 16), 256, GEMM_SMEM>>>(outp);
}

// round 12
// speedup vs baseline: 1.5580x; 1.5580x over previous
#include <cuda_runtime.h>
#include <mma.h>
#include <math.h>

using namespace nvcuda;

#define LL 2048
#define DD 2048
#define NH 32
#define NKV 8
#define HDIM 64
#define QKVN 3072

__device__ float g_qkv[LL * QKVN];
__device__ float g_attn[LL * DD];

// ---------------------------------------------------------------------------
// cp.async helpers
// ---------------------------------------------------------------------------
__device__ __forceinline__ void cp_async16(void* smem, const void* gmem) {
    unsigned saddr = (unsigned)__cvta_generic_to_shared(smem);
    asm volatile("cp.async.cg.shared.global [%0], [%1], 16;\n" :: "r"(saddr), "l"(gmem));
}
__device__ __forceinline__ void cp_commit() {
    asm volatile("cp.async.commit_group;\n");
}
template <int N>
__device__ __forceinline__ void cp_wait() {
    asm volatile("cp.async.wait_group %0;\n" :: "n"(N));
}

// ---------------------------------------------------------------------------
// In-place tf32 purify (idempotent: tf32(tf32(x)) == tf32(x)), 4x float4 ILP
// ---------------------------------------------------------------------------
__global__ void purify_kernel(float* __restrict__ p, int n4)
{
    float4* p4 = (float4*)p;
    int i = blockIdx.x * blockDim.x + threadIdx.x;
    int stride = gridDim.x * blockDim.x;
    for (; i + 3 * stride < n4; i += 4 * stride) {
        float4 v0 = p4[i];
        float4 v1 = p4[i + stride];
        float4 v2 = p4[i + 2 * stride];
        float4 v3 = p4[i + 3 * stride];
#define RND4(v)                              \
        v.x = wmma::__float_to_tf32(v.x);    \
        v.y = wmma::__float_to_tf32(v.y);    \
        v.z = wmma::__float_to_tf32(v.z);    \
        v.w = wmma::__float_to_tf32(v.w)
        RND4(v0); RND4(v1); RND4(v2); RND4(v3);
        p4[i] = v0;
        p4[i + stride] = v1;
        p4[i + 2 * stride] = v2;
        p4[i + 3 * stride] = v3;
    }
    for (; i < n4; i += stride) {
        float4 v = p4[i];
        RND4(v);
        p4[i] = v;
#undef RND4
    }
}

// ---------------------------------------------------------------------------
// WMMA typedefs (tf32, m16n16k8)
// ---------------------------------------------------------------------------
typedef wmma::fragment<wmma::matrix_a, 16, 16, 8, wmma::precision::tf32, wmma::row_major> AFrag;
typedef wmma::fragment<wmma::matrix_b, 16, 16, 8, wmma::precision::tf32, wmma::row_major> BFrag;
typedef wmma::fragment<wmma::matrix_b, 16, 16, 8, wmma::precision::tf32, wmma::col_major> BFragT;
typedef wmma::fragment<wmma::accumulator, 16, 16, 8, float> CFrag;

__device__ __forceinline__ void frag_to_tf32(float* x, int n) {
#pragma unroll
    for (int t = 0; t < n; t++) x[t] = wmma::__float_to_tf32(x[t]);
}

// ---------------------------------------------------------------------------
// Double-buffered tf32 GEMM: 128x128 tile, KC=32, 256 threads, 8 warps (32x64)
// All inputs tf32-valued -> no per-fragment cvt in mainloop.
// ---------------------------------------------------------------------------
#define KC 32
#define A_LD 40
#define B_LD 136
#define GEMM_SMEM ((2 * 128 * A_LD + 2 * KC * B_LD) * 4)  // 75,776 B

template <bool ROUND_OUT>
__device__ __forceinline__ void gemm_pipe(
    const float* __restrict__ A, const float* __restrict__ Bp, int ldb, int cb,
    float* __restrict__ C, int ldc, int r0, int c0)
{
    extern __shared__ float sh[];
    float* As = sh;
    float* Bs = sh + 2 * 128 * A_LD;

    const int tid = threadIdx.x;
    const int w = tid >> 5;
    const int wm = w & 3;
    const int wn = w >> 2;

    CFrag acc[2][4];
#pragma unroll
    for (int i = 0; i < 2; i++)
#pragma unroll
        for (int j = 0; j < 4; j++) wmma::fill_fragment(acc[i][j], 0.f);

#define G_LOAD_STAGE(s, k0)                                                         \
    do {                                                                            \
        _Pragma("unroll") for (int it = 0; it < 4; it++) {                          \
            int lin = tid + it * 256;                                               \
            int row = lin >> 3;                                                     \
            int c4 = (lin & 7) * 4;                                                 \
            cp_async16(&As[(s) * 128 * A_LD + row * A_LD + c4],                     \
                       A + (size_t)(r0 + row) * DD + (k0) + c4);                    \
        }                                                                           \
        _Pragma("unroll") for (int it = 0; it < 4; it++) {                          \
            int lin = tid + it * 256;                                               \
            int row = lin >> 5;                                                     \
            int c4 = (lin & 31) * 4;                                                \
            cp_async16(&Bs[(s) * KC * B_LD + row * B_LD + c4],                      \
                       Bp + (size_t)((k0) + row) * ldb + cb + c4);                  \
        }                                                                           \
    } while (0)

    G_LOAD_STAGE(0, 0);
    cp_commit();

    int s = 0;
    for (int k0 = 0; k0 < DD; k0 += KC, s ^= 1) {
        if (k0 + KC < DD) G_LOAD_STAGE(s ^ 1, k0 + KC);
        cp_commit();
        cp_wait<1>();
        __syncthreads();

        const float* Ab = &As[s * 128 * A_LD];
        const float* Bb = &Bs[s * KC * B_LD];
#pragma unroll
        for (int ks = 0; ks < 4; ks++) {
            AFrag a[2];
            BFrag b[4];
#pragma unroll
            for (int i = 0; i < 2; i++)
                wmma::load_matrix_sync(a[i], Ab + (wm * 32 + i * 16) * A_LD + ks * 8, A_LD);
#pragma unroll
            for (int j = 0; j < 4; j++)
                wmma::load_matrix_sync(b[j], Bb + (ks * 8) * B_LD + wn * 64 + j * 16, B_LD);
#pragma unroll
            for (int i = 0; i < 2; i++)
#pragma unroll
                for (int j = 0; j < 4; j++)
                    wmma::mma_sync(acc[i][j], a[i], b[j], acc[i][j]);
        }
        __syncthreads();
    }

#pragma unroll
    for (int i = 0; i < 2; i++)
#pragma unroll
        for (int j = 0; j < 4; j++) {
            if (ROUND_OUT) frag_to_tf32(acc[i][j].x, acc[i][j].num_elements);
            wmma::store_matrix_sync(
                C + (size_t)(r0 + wm * 32 + i * 16) * ldc + c0 + wn * 64 + j * 16,
                acc[i][j], ldc, wmma::mem_row_major);
        }
#undef G_LOAD_STAGE
}

__global__ __launch_bounds__(256, 2) void gemm_qkv_kernel(
    const float* __restrict__ x, const float* __restrict__ wq,
    const float* __restrict__ wk, const float* __restrict__ wv)
{
    const int r0 = blockIdx.y * 128;
    const int c0 = blockIdx.x * 128;
    const float* Bp; int ldb; int cb;
    if (c0 < 2048)      { Bp = wq; ldb = 2048; cb = c0; }
    else if (c0 < 2560) { Bp = wk; ldb = 512;  cb = c0 - 2048; }
    else                { Bp = wv; ldb = 512;  cb = c0 - 2560; }
    gemm_pipe<true>(x, Bp, ldb, cb, g_qkv, QKVN, r0, c0);
}

__global__ __launch_bounds__(256, 2) void gemm_out_kernel(
    const float* __restrict__ wo, float* __restrict__ outp)
{
    gemm_pipe<false>(g_attn, wo, DD, blockIdx.x * 128, outp, DD,
                     blockIdx.y * 128, blockIdx.x * 128);
}

// ---------------------------------------------------------------------------
// RoPE (in-place, outputs rounded to tf32)
// ---------------------------------------------------------------------------
__global__ void rope_kernel(const float* __restrict__ fc, const float* __restrict__ fs)
{
    int idx = blockIdx.x * blockDim.x + threadIdx.x;
    const int total = LL * (NH + NKV) * (HDIM / 2);
    if (idx >= total) return;
    int i    = idx & 31;
    int rem  = idx >> 5;
    int head = rem % (NH + NKV);
    int l    = rem / (NH + NKV);
    int col  = (head < NH) ? head * HDIM + 2 * i
                           : 2048 + (head - NH) * HDIM + 2 * i;
    float* p = g_qkv + (size_t)l * QKVN + col;
    float xr = p[0], xi = p[1];
    float c = fc[l * 32 + i], s = fs[l * 32 + i];
    p[0] = wmma::__float_to_tf32(xr * c - xi * s);
    p[1] = wmma::__float_to_tf32(xr * s + xi * c);
}

// ---------------------------------------------------------------------------
// Flash attention: 128-row Q tile x 64-col K tiles, 512 threads (16 warps),
// tf32 WMMA (Q/K/V tf32-valued; only P fragments need cvt),
// double-buffered cp.async K/V.
// ---------------------------------------------------------------------------
#define T_LD 72
#define ATT_SMEM ((3 * 128 * T_LD + 4 * 64 * T_LD + 2 * 128) * 4)

__global__ __launch_bounds__(512) void attn_kernel()
{
    const int h   = blockIdx.x;
    const int qt  = (gridDim.y - 1) - blockIdx.y;   // big tiles first
    const int kvh = h >> 2;

    extern __shared__ float sm[];
    float* Qs = sm;                      // [128][T_LD] (pre-scaled)
    float* Ss = Qs + 128 * T_LD;         // [128][T_LD]
    float* Os = Ss + 128 * T_LD;         // [128][T_LD]
    float* Ks = Os + 128 * T_LD;         // [2][64][T_LD]
    float* Vs = Ks + 2 * 64 * T_LD;      // [2][64][T_LD]
    float* m_s = Vs + 2 * 64 * T_LD;     // [128]
    float* l_s = m_s + 128;

    const int tid = threadIdx.x;
    const int w  = tid >> 5;
    const int wm = w & 7;        // 16-row slab
    const int wn = w >> 3;       // 32-col slab
    const int qrow = tid >> 2;   // 0..127
    const int part = tid & 3;

#define A_LOAD_KV(s, kt)                                                            \
    do {                                                                            \
        const float* base0 = g_qkv + (size_t)((kt) * 64) * QKVN;                    \
        _Pragma("unroll") for (int it = 0; it < 2; it++) {                          \
            int lin = tid + it * 512;                                               \
            int row = lin >> 4;                                                     \
            int c4 = (lin & 15) * 4;                                                \
            const float* rb = base0 + (size_t)row * QKVN;                           \
            cp_async16(&Ks[(s) * 64 * T_LD + row * T_LD + c4],                      \
                       rb + 2048 + kvh * HDIM + c4);                                \
            cp_async16(&Vs[(s) * 64 * T_LD + row * T_LD + c4],                      \
                       rb + 2560 + kvh * HDIM + c4);                                \
        }                                                                           \
    } while (0)

    A_LOAD_KV(0, 0);
    cp_commit();

    // load Q (scaled by 1/8 — exact power of two keeps tf32-ness)
#pragma unroll
    for (int it = 0; it < 4; it++) {
        int lin = tid + it * 512;
        int row = lin >> 4;
        int c4  = (lin & 15) * 4;
        float4 v = *(const float4*)(g_qkv + (size_t)(qt * 128 + row) * QKVN + h * HDIM + c4);
        *(float4*)(&Qs[row * T_LD + c4]) =
            make_float4(v.x * 0.125f, v.y * 0.125f, v.z * 0.125f, v.w * 0.125f);
    }
    // zero O
#pragma unroll
    for (int it = 0; it < 16; it++) {
        int lin = tid + it * 512;
        Os[(lin >> 6) * T_LD + (lin & 63)] = 0.f;
    }
    if (tid < 128) { m_s[tid] = -1e30f; l_s[tid] = 0.f; }

    const int nkt = 2 * qt + 2;
    int s = 0;
    for (int kt = 0; kt < nkt; kt++, s ^= 1) {
        if (kt + 1 < nkt) A_LOAD_KV(s ^ 1, kt + 1);
        cp_commit();
        cp_wait<1>();
        __syncthreads();

        const float* Kb = &Ks[s * 64 * T_LD];
        const float* Vb = &Vs[s * 64 * T_LD];

        // S = Qs @ K^T   (Q, K already tf32-valued)
        {
            CFrag sacc[2];
            wmma::fill_fragment(sacc[0], 0.f);
            wmma::fill_fragment(sacc[1], 0.f);
#pragma unroll
            for (int ks = 0; ks < 8; ks++) {
                AFrag a;
                wmma::load_matrix_sync(a, &Qs[(wm * 16) * T_LD + ks * 8], T_LD);
#pragma unroll
                for (int j = 0; j < 2; j++) {
                    BFragT b;
                    wmma::load_matrix_sync(b, Kb + (wn * 32 + j * 16) * T_LD + ks * 8, T_LD);
                    wmma::mma_sync(sacc[j], a, b, sacc[j]);
                }
            }
#pragma unroll
            for (int j = 0; j < 2; j++)
                wmma::store_matrix_sync(&Ss[(wm * 16) * T_LD + wn * 32 + j * 16],
                                        sacc[j], T_LD, wmma::mem_row_major);
        }
        __syncthreads();

        // online softmax + O rescale: quad of 4 threads per row, 16 cols each
        {
            const bool tail = (kt >= 2 * qt);
            const int qi = qt * 128 + qrow;
            float vals[16];
            float pm = -1e30f;
#pragma unroll
            for (int kk = 0; kk < 16; kk++) {
                float v = Ss[qrow * T_LD + part * 16 + kk];
                if (tail && (kt * 64 + part * 16 + kk > qi)) v = -1e30f;
                vals[kk] = v;
                pm = fmaxf(pm, v);
            }
            pm = fmaxf(pm, __shfl_xor_sync(0xffffffffu, pm, 1));
            pm = fmaxf(pm, __shfl_xor_sync(0xffffffffu, pm, 2));
            float m_old = m_s[qrow];
            float m_new = fmaxf(m_old, pm);
            float ps = 0.f;
#pragma unroll
            for (int kk = 0; kk < 16; kk++) {
                float e = __expf(vals[kk] - m_new);
                Ss[qrow * T_LD + part * 16 + kk] = e;
                ps += e;
            }
            ps += __shfl_xor_sync(0xffffffffu, ps, 1);
            ps += __shfl_xor_sync(0xffffffffu, ps, 2);
            float alpha = __expf(m_old - m_new);
#pragma unroll
            for (int kk = 0; kk < 16; kk++)
                Os[qrow * T_LD + part * 16 + kk] *= alpha;
            if (part == 0) {
                l_s[qrow] = l_s[qrow] * alpha + ps;
                m_s[qrow] = m_new;
            }
        }
        __syncthreads();

        // O += P @ V   (P needs cvt; V already tf32-valued)
        {
#pragma unroll
            for (int j = 0; j < 2; j++) {
                CFrag oacc;
                wmma::load_matrix_sync(oacc, &Os[(wm * 16) * T_LD + wn * 32 + j * 16],
                                       T_LD, wmma::mem_row_major);
#pragma unroll
                for (int ks = 0; ks < 8; ks++) {
                    AFrag a;
                    wmma::load_matrix_sync(a, &Ss[(wm * 16) * T_LD + ks * 8], T_LD);
                    frag_to_tf32(a.x, a.num_elements);
                    BFrag b;
                    wmma::load_matrix_sync(b, Vb + (ks * 8) * T_LD + wn * 32 + j * 16, T_LD);
                    wmma::mma_sync(oacc, a, b, oacc);
                }
                wmma::store_matrix_sync(&Os[(wm * 16) * T_LD + wn * 32 + j * 16],
                                        oacc, T_LD, wmma::mem_row_major);
            }
        }
        __syncthreads();
    }

    // final normalize + write (rounded to tf32 for gemm_out)
#pragma unroll
    for (int it = 0; it < 16; it++) {
        int lin = tid + it * 512;
        int row = lin >> 6;
        int col = lin & 63;
        g_attn[(size_t)(qt * 128 + row) * DD + h * HDIM + col] =
            wmma::__float_to_tf32(Os[row * T_LD + col] / l_s[row]);
    }
#undef A_LOAD_KV
}

// ---------------------------------------------------------------------------
extern "C" void kernel_launch(void* const* d_in, const int* in_sizes, int n_in,
                              void* d_out, int out_size)
{
    float* x  = (float*)d_in[0];
    float* wq = (float*)d_in[1];
    float* wk = (float*)d_in[2];
    float* wv = (float*)d_in[3];
    float* wo = (float*)d_in[4];
    const float* fc = (const float*)d_in[5];
    const float* fs = (const float*)d_in[6];
    float* outp = (float*)d_out;

    cudaFuncSetAttribute(gemm_qkv_kernel, cudaFuncAttributeMaxDynamicSharedMemorySize, GEMM_SMEM);
    cudaFuncSetAttribute(gemm_out_kernel, cudaFuncAttributeMaxDynamicSharedMemorySize, GEMM_SMEM);
    cudaFuncSetAttribute(attn_kernel, cudaFuncAttributeMaxDynamicSharedMemorySize, ATT_SMEM);

    // In-place tf32 purify of GEMM inputs (idempotent -> deterministic across
    // the correctness call and every graph replay; no extra memory footprint).
    purify_kernel<<<1024, 256>>>(x,  LL * DD / 4);
    purify_kernel<<<1024, 256>>>(wq, DD * 2048 / 4);
    purify_kernel<<<512,  256>>>(wk, DD * 512 / 4);
    purify_kernel<<<512,  256>>>(wv, DD * 512 / 4);
    purify_kernel<<<1024, 256>>>(wo, DD * DD / 4);

    gemm_qkv_kernel<<<dim3(24, 16), 256, GEMM_SMEM>>>(x, wq, wk, wv);

    int total = LL * (NH + NKV) * (HDIM / 2);
    rope_kernel<<<(total + 255) / 256, 256>>>(fc, fs);

    attn_kernel<<<dim3(32, 16), 512, ATT_SMEM>>>();

    gemm_out_kernel<<<dim3(16, 16), 256, GEMM_SMEM>>>(wo, outp);
}

// round 13
// speedup vs baseline: 1.9835x; 1.2731x over previous
#include <cuda_runtime.h>
#include <mma.h>
#include <math.h>

using namespace nvcuda;

#define LL 2048
#define DD 2048
#define NH 32
#define NKV 8
#define HDIM 64
#define QKVN 3072

__device__ float g_qkv[LL * QKVN];
__device__ float g_attn[LL * DD];

// ---------------------------------------------------------------------------
// cp.async helpers
// ---------------------------------------------------------------------------
__device__ __forceinline__ void cp_async16(void* smem, const void* gmem) {
    unsigned saddr = (unsigned)__cvta_generic_to_shared(smem);
    asm volatile("cp.async.cg.shared.global [%0], [%1], 16;\n" :: "r"(saddr), "l"(gmem));
}
__device__ __forceinline__ void cp_commit() {
    asm volatile("cp.async.commit_group;\n");
}
template <int N>
__device__ __forceinline__ void cp_wait() {
    asm volatile("cp.async.wait_group %0;\n" :: "n"(N));
}

// ---------------------------------------------------------------------------
// In-place tf32 purify (idempotent), 4x float4 ILP
// ---------------------------------------------------------------------------
__global__ void purify_kernel(float* __restrict__ p, int n4)
{
    float4* p4 = (float4*)p;
    int i = blockIdx.x * blockDim.x + threadIdx.x;
    int stride = gridDim.x * blockDim.x;
    for (; i + 3 * stride < n4; i += 4 * stride) {
        float4 v0 = p4[i];
        float4 v1 = p4[i + stride];
        float4 v2 = p4[i + 2 * stride];
        float4 v3 = p4[i + 3 * stride];
#define RND4(v)                              \
        v.x = wmma::__float_to_tf32(v.x);    \
        v.y = wmma::__float_to_tf32(v.y);    \
        v.z = wmma::__float_to_tf32(v.z);    \
        v.w = wmma::__float_to_tf32(v.w)
        RND4(v0); RND4(v1); RND4(v2); RND4(v3);
        p4[i] = v0;
        p4[i + stride] = v1;
        p4[i + 2 * stride] = v2;
        p4[i + 3 * stride] = v3;
    }
    for (; i < n4; i += stride) {
        float4 v = p4[i];
        RND4(v);
        p4[i] = v;
#undef RND4
    }
}

// ---------------------------------------------------------------------------
// WMMA typedefs (tf32, m16n16k8) for the projection GEMMs
// ---------------------------------------------------------------------------
typedef wmma::fragment<wmma::matrix_a, 16, 16, 8, wmma::precision::tf32, wmma::row_major> AFrag;
typedef wmma::fragment<wmma::matrix_b, 16, 16, 8, wmma::precision::tf32, wmma::row_major> BFrag;
typedef wmma::fragment<wmma::accumulator, 16, 16, 8, float> CFrag;

__device__ __forceinline__ void frag_to_tf32(float* x, int n) {
#pragma unroll
    for (int t = 0; t < n; t++) x[t] = wmma::__float_to_tf32(x[t]);
}

// ---------------------------------------------------------------------------
// Double-buffered tf32 GEMM: 128x128 tile, KC=32, 256 threads (unchanged)
// ---------------------------------------------------------------------------
#define KC 32
#define A_LD 40
#define B_LD 136
#define GEMM_SMEM ((2 * 128 * A_LD + 2 * KC * B_LD) * 4)  // 75,776 B

template <bool ROUND_OUT>
__device__ __forceinline__ void gemm_pipe(
    const float* __restrict__ A, const float* __restrict__ Bp, int ldb, int cb,
    float* __restrict__ C, int ldc, int r0, int c0)
{
    extern __shared__ float sh[];
    float* As = sh;
    float* Bs = sh + 2 * 128 * A_LD;

    const int tid = threadIdx.x;
    const int w = tid >> 5;
    const int wm = w & 3;
    const int wn = w >> 2;

    CFrag acc[2][4];
#pragma unroll
    for (int i = 0; i < 2; i++)
#pragma unroll
        for (int j = 0; j < 4; j++) wmma::fill_fragment(acc[i][j], 0.f);

#define G_LOAD_STAGE(s, k0)                                                         \
    do {                                                                            \
        _Pragma("unroll") for (int it = 0; it < 4; it++) {                          \
            int lin = tid + it * 256;                                               \
            int row = lin >> 3;                                                     \
            int c4 = (lin & 7) * 4;                                                 \
            cp_async16(&As[(s) * 128 * A_LD + row * A_LD + c4],                     \
                       A + (size_t)(r0 + row) * DD + (k0) + c4);                    \
        }                                                                           \
        _Pragma("unroll") for (int it = 0; it < 4; it++) {                          \
            int lin = tid + it * 256;                                               \
            int row = lin >> 5;                                                     \
            int c4 = (lin & 31) * 4;                                                \
            cp_async16(&Bs[(s) * KC * B_LD + row * B_LD + c4],                      \
                       Bp + (size_t)((k0) + row) * ldb + cb + c4);                  \
        }                                                                           \
    } while (0)

    G_LOAD_STAGE(0, 0);
    cp_commit();

    int s = 0;
    for (int k0 = 0; k0 < DD; k0 += KC, s ^= 1) {
        if (k0 + KC < DD) G_LOAD_STAGE(s ^ 1, k0 + KC);
        cp_commit();
        cp_wait<1>();
        __syncthreads();

        const float* Ab = &As[s * 128 * A_LD];
        const float* Bb = &Bs[s * KC * B_LD];
#pragma unroll
        for (int ks = 0; ks < 4; ks++) {
            AFrag a[2];
            BFrag b[4];
#pragma unroll
            for (int i = 0; i < 2; i++)
                wmma::load_matrix_sync(a[i], Ab + (wm * 32 + i * 16) * A_LD + ks * 8, A_LD);
#pragma unroll
            for (int j = 0; j < 4; j++)
                wmma::load_matrix_sync(b[j], Bb + (ks * 8) * B_LD + wn * 64 + j * 16, B_LD);
#pragma unroll
            for (int i = 0; i < 2; i++)
#pragma unroll
                for (int j = 0; j < 4; j++)
                    wmma::mma_sync(acc[i][j], a[i], b[j], acc[i][j]);
        }
        __syncthreads();
    }

#pragma unroll
    for (int i = 0; i < 2; i++)
#pragma unroll
        for (int j = 0; j < 4; j++) {
            if (ROUND_OUT) frag_to_tf32(acc[i][j].x, acc[i][j].num_elements);
            wmma::store_matrix_sync(
                C + (size_t)(r0 + wm * 32 + i * 16) * ldc + c0 + wn * 64 + j * 16,
                acc[i][j], ldc, wmma::mem_row_major);
        }
#undef G_LOAD_STAGE
}

__global__ __launch_bounds__(256, 2) void gemm_qkv_kernel(
    const float* __restrict__ x, const float* __restrict__ wq,
    const float* __restrict__ wk, const float* __restrict__ wv)
{
    const int r0 = blockIdx.y * 128;
    const int c0 = blockIdx.x * 128;
    const float* Bp; int ldb; int cb;
    if (c0 < 2048)      { Bp = wq; ldb = 2048; cb = c0; }
    else if (c0 < 2560) { Bp = wk; ldb = 512;  cb = c0 - 2048; }
    else                { Bp = wv; ldb = 512;  cb = c0 - 2560; }
    gemm_pipe<true>(x, Bp, ldb, cb, g_qkv, QKVN, r0, c0);
}

__global__ __launch_bounds__(256, 2) void gemm_out_kernel(
    const float* __restrict__ wo, float* __restrict__ outp)
{
    gemm_pipe<false>(g_attn, wo, DD, blockIdx.x * 128, outp, DD,
                     blockIdx.y * 128, blockIdx.x * 128);
}

// ---------------------------------------------------------------------------
// RoPE (in-place, outputs rounded to tf32)
// ---------------------------------------------------------------------------
__global__ void rope_kernel(const float* __restrict__ fc, const float* __restrict__ fs)
{
    int idx = blockIdx.x * blockDim.x + threadIdx.x;
    const int total = LL * (NH + NKV) * (HDIM / 2);
    if (idx >= total) return;
    int i    = idx & 31;
    int rem  = idx >> 5;
    int head = rem % (NH + NKV);
    int l    = rem / (NH + NKV);
    int col  = (head < NH) ? head * HDIM + 2 * i
                           : 2048 + (head - NH) * HDIM + 2 * i;
    float* p = g_qkv + (size_t)l * QKVN + col;
    float xr = p[0], xi = p[1];
    float c = fc[l * 32 + i], s = fs[l * 32 + i];
    p[0] = wmma::__float_to_tf32(xr * c - xi * s);
    p[1] = wmma::__float_to_tf32(xr * s + xi * c);
}

// ---------------------------------------------------------------------------
// FlashAttention-2 style: raw mma.sync.m16n8k8.tf32, S and O in registers.
// 256 threads (8 warps); warp owns 16 q-rows x 64 k-cols. Q tile = 128 rows.
// 3-stage cp.async KV ring -> ONE __syncthreads per kt tile.
// T_LD = 68: conflict-free for Q/K b-frag loads (addr%32 = 4*row + col lane map)
// ---------------------------------------------------------------------------
#define T_LD 68
#define ATT_SMEM ((128 * T_LD + 3 * 2 * 64 * T_LD + 8 * 16 * T_LD) * 4)  // 174,080 B

__device__ __forceinline__ void mma_tf32(float* d, const unsigned* a, const unsigned* b)
{
    asm volatile(
        "mma.sync.aligned.m16n8k8.row.col.f32.tf32.tf32.f32 "
        "{%0,%1,%2,%3}, {%4,%5,%6,%7}, {%8,%9}, {%0,%1,%2,%3};\n"
        : "+f"(d[0]), "+f"(d[1]), "+f"(d[2]), "+f"(d[3])
        : "r"(a[0]), "r"(a[1]), "r"(a[2]), "r"(a[3]), "r"(b[0]), "r"(b[1]));
}
__device__ __forceinline__ unsigned f_bits(const float* p) {
    return __float_as_uint(*p);
}

__global__ __launch_bounds__(256) void attn_kernel()
{
    const int h   = blockIdx.x;
    const int qt  = (gridDim.y - 1) - blockIdx.y;   // big tiles first
    const int kvh = h >> 2;

    extern __shared__ float sm[];
    float* Qs = sm;                           // [128][T_LD] pre-scaled 1/8
    float* KV = Qs + 128 * T_LD;              // [3 stages][K|V][64][T_LD]
    float* Ps = KV + 3 * 2 * 64 * T_LD;       // [8 warps][16][T_LD]

    const int tid  = threadIdx.x;
    const int w    = tid >> 5;
    const int lane = tid & 31;
    const int grp  = lane >> 2;   // 0..7   (row within 8-row group)
    const int tig  = lane & 3;    // 0..3   (col group)
    float* Pw = Ps + w * 16 * T_LD;

    const int rg0 = qt * 128 + w * 16 + grp;      // global q row (slot 0)
    const int rg1 = rg0 + 8;                      // global q row (slot 1)

#define KV_STAGE(st) (KV + (st) * 2 * 64 * T_LD)
#define LOAD_KV(st, kt)                                                           \
    do {                                                                          \
        float* Kd = KV_STAGE(st);                                                 \
        float* Vd = Kd + 64 * T_LD;                                               \
        const float* base0 = g_qkv + (size_t)((kt) * 64) * QKVN;                  \
        _Pragma("unroll") for (int it = 0; it < 4; it++) {                        \
            int lin = tid + it * 256;                                             \
            int row = lin >> 4;                                                   \
            int c4  = (lin & 15) * 4;                                             \
            const float* rb = base0 + (size_t)row * QKVN;                         \
            cp_async16(&Kd[row * T_LD + c4], rb + 2048 + kvh * HDIM + c4);        \
            cp_async16(&Vd[row * T_LD + c4], rb + 2560 + kvh * HDIM + c4);        \
        }                                                                         \
    } while (0)

    // prefetch KV tile 0
    LOAD_KV(0, 0);
    cp_commit();

    // load Q tile (scaled by 1/8; power of two keeps tf32-ness)
#pragma unroll
    for (int it = 0; it < 8; it++) {
        int lin = tid + it * 256;
        int row = lin >> 4;
        int c4  = (lin & 15) * 4;
        float4 v = *(const float4*)(g_qkv + (size_t)(qt * 128 + row) * QKVN + h * HDIM + c4);
        *(float4*)(&Qs[row * T_LD + c4]) =
            make_float4(v.x * 0.125f, v.y * 0.125f, v.z * 0.125f, v.w * 0.125f);
    }

    float oacc[8][4];
#pragma unroll
    for (int n = 0; n < 8; n++)
#pragma unroll
        for (int e = 0; e < 4; e++) oacc[n][e] = 0.f;
    float m0 = -1e30f, m1 = -1e30f, l0 = 0.f, l1 = 0.f;

    const int nkt = 2 * qt + 2;
    for (int kt = 0; kt < nkt; kt++) {
        const int st = kt % 3;
        if (kt + 1 < nkt) LOAD_KV((kt + 1) % 3, kt + 1);
        cp_commit();
        cp_wait<1>();
        __syncthreads();

        const float* Kb = KV_STAGE(st);
        const float* Vb = Kb + 64 * T_LD;

        // ---- S = Q @ K^T (registers) ----
        float sacc[8][4];
#pragma unroll
        for (int n = 0; n < 8; n++)
#pragma unroll
            for (int e = 0; e < 4; e++) sacc[n][e] = 0.f;

#pragma unroll
        for (int ks = 0; ks < 8; ks++) {
            const int qr0 = (w * 16 + grp) * T_LD + ks * 8 + tig;
            const int qr1 = qr0 + 8 * T_LD;
            unsigned a[4];
            a[0] = f_bits(&Qs[qr0]);
            a[1] = f_bits(&Qs[qr1]);
            a[2] = f_bits(&Qs[qr0 + 4]);
            a[3] = f_bits(&Qs[qr1 + 4]);
#pragma unroll
            for (int n = 0; n < 8; n++) {
                const int kb = (n * 8 + grp) * T_LD + ks * 8 + tig;
                unsigned b[2];
                b[0] = f_bits(&Kb[kb]);
                b[1] = f_bits(&Kb[kb + 4]);
                mma_tf32(sacc[n], a, b);
            }
        }

        // ---- softmax in registers (4 lanes per row) ----
        {
            const int cbase = kt * 64 + 2 * tig;
            float mx0 = -1e30f, mx1 = -1e30f;
#pragma unroll
            for (int n = 0; n < 8; n++) {
                int cg = cbase + n * 8;
                if (cg     > rg0) sacc[n][0] = -1e30f;
                if (cg + 1 > rg0) sacc[n][1] = -1e30f;
                if (cg     > rg1) sacc[n][2] = -1e30f;
                if (cg + 1 > rg1) sacc[n][3] = -1e30f;
                mx0 = fmaxf(mx0, fmaxf(sacc[n][0], sacc[n][1]));
                mx1 = fmaxf(mx1, fmaxf(sacc[n][2], sacc[n][3]));
            }
            mx0 = fmaxf(mx0, __shfl_xor_sync(0xffffffffu, mx0, 1));
            mx0 = fmaxf(mx0, __shfl_xor_sync(0xffffffffu, mx0, 2));
            mx1 = fmaxf(mx1, __shfl_xor_sync(0xffffffffu, mx1, 1));
            mx1 = fmaxf(mx1, __shfl_xor_sync(0xffffffffu, mx1, 2));
            float mn0 = fmaxf(m0, mx0), mn1 = fmaxf(m1, mx1);
            float al0 = __expf(m0 - mn0), al1 = __expf(m1 - mn1);
            float ps0 = 0.f, ps1 = 0.f;
#pragma unroll
            for (int n = 0; n < 8; n++) {
                float p0 = __expf(sacc[n][0] - mn0);
                float p1 = __expf(sacc[n][1] - mn0);
                float p2 = __expf(sacc[n][2] - mn1);
                float p3 = __expf(sacc[n][3] - mn1);
                ps0 += p0 + p1; ps1 += p2 + p3;
                // store P (tf32-rounded) to warp-private slab
                float2* d0 = (float2*)&Pw[grp * T_LD + n * 8 + 2 * tig];
                float2* d1 = (float2*)&Pw[(grp + 8) * T_LD + n * 8 + 2 * tig];
                *d0 = make_float2(wmma::__float_to_tf32(p0), wmma::__float_to_tf32(p1));
                *d1 = make_float2(wmma::__float_to_tf32(p2), wmma::__float_to_tf32(p3));
                // rescale O
                oacc[n][0] *= al0; oacc[n][1] *= al0;
                oacc[n][2] *= al1; oacc[n][3] *= al1;
            }
            ps0 += __shfl_xor_sync(0xffffffffu, ps0, 1);
            ps0 += __shfl_xor_sync(0xffffffffu, ps0, 2);
            ps1 += __shfl_xor_sync(0xffffffffu, ps1, 1);
            ps1 += __shfl_xor_sync(0xffffffffu, ps1, 2);
            l0 = l0 * al0 + ps0;
            l1 = l1 * al1 + ps1;
            m0 = mn0; m1 = mn1;
        }
        __syncwarp();

        // ---- O += P @ V ----
#pragma unroll
        for (int kc = 0; kc < 8; kc++) {
            const int pr0 = grp * T_LD + kc * 8 + tig;
            const int pr1 = pr0 + 8 * T_LD;
            unsigned a[4];
            a[0] = f_bits(&Pw[pr0]);
            a[1] = f_bits(&Pw[pr1]);
            a[2] = f_bits(&Pw[pr0 + 4]);
            a[3] = f_bits(&Pw[pr1 + 4]);
#pragma unroll
            for (int n = 0; n < 8; n++) {
                const int vb = (kc * 8 + tig) * T_LD + n * 8 + grp;
                unsigned b[2];
                b[0] = f_bits(&Vb[vb]);
                b[1] = f_bits(&Vb[vb + 4 * T_LD]);
                mma_tf32(oacc[n], a, b);
            }
        }
        // next iteration's sync covers cross-warp KV stage reuse (3-stage ring)
    }

    // ---- final normalize + write (tf32-rounded for gemm_out) ----
    {
        float inv0 = 1.f / l0, inv1 = 1.f / l1;
#pragma unroll
        for (int n = 0; n < 8; n++) {
            int col = h * HDIM + n * 8 + 2 * tig;
            float2* d0 = (float2*)&g_attn[(size_t)rg0 * DD + col];
            float2* d1 = (float2*)&g_attn[(size_t)rg1 * DD + col];
            *d0 = make_float2(wmma::__float_to_tf32(oacc[n][0] * inv0),
                              wmma::__float_to_tf32(oacc[n][1] * inv0));
            *d1 = make_float2(wmma::__float_to_tf32(oacc[n][2] * inv1),
                              wmma::__float_to_tf32(oacc[n][3] * inv1));
        }
    }
#undef LOAD_KV
#undef KV_STAGE
}

// ---------------------------------------------------------------------------
extern "C" void kernel_launch(void* const* d_in, const int* in_sizes, int n_in,
                              void* d_out, int out_size)
{
    float* x  = (float*)d_in[0];
    float* wq = (float*)d_in[1];
    float* wk = (float*)d_in[2];
    float* wv = (float*)d_in[3];
    float* wo = (float*)d_in[4];
    const float* fc = (const float*)d_in[5];
    const float* fs = (const float*)d_in[6];
    float* outp = (float*)d_out;

    cudaFuncSetAttribute(gemm_qkv_kernel, cudaFuncAttributeMaxDynamicSharedMemorySize, GEMM_SMEM);
    cudaFuncSetAttribute(gemm_out_kernel, cudaFuncAttributeMaxDynamicSharedMemorySize, GEMM_SMEM);
    cudaFuncSetAttribute(attn_kernel, cudaFuncAttributeMaxDynamicSharedMemorySize, ATT_SMEM);

    // In-place tf32 purify (idempotent -> deterministic across graph replays)
    purify_kernel<<<1024, 256>>>(x,  LL * DD / 4);
    purify_kernel<<<1024, 256>>>(wq, DD * 2048 / 4);
    purify_kernel<<<512,  256>>>(wk, DD * 512 / 4);
    purify_kernel<<<512,  256>>>(wv, DD * 512 / 4);
    purify_kernel<<<1024, 256>>>(wo, DD * DD / 4);

    gemm_qkv_kernel<<<dim3(24, 16), 256, GEMM_SMEM>>>(x, wq, wk, wv);

    int total = LL * (NH + NKV) * (HDIM / 2);
    rope_kernel<<<(total + 255) / 256, 256>>>(fc, fs);

    attn_kernel<<<dim3(32, 16), 256, ATT_SMEM>>>();

    gemm_out_kernel<<<dim3(16, 16), 256, GEMM_SMEM>>>(wo, outp);
}

// round 15
// speedup vs baseline: 3.2180x; 1.6224x over previous
#include <cuda_runtime.h>
#include <mma.h>
#include <math.h>

using namespace nvcuda;

#define LL 2048
#define DD 2048
#define NH 32
#define NKV 8
#define HDIM 64
#define QKVN 3072

__device__ float g_qkv[LL * QKVN];
__device__ float g_attn[LL * DD];

// ---------------------------------------------------------------------------
// cp.async helpers
// ---------------------------------------------------------------------------
__device__ __forceinline__ void cp_async16(void* smem, const void* gmem) {
    unsigned saddr = (unsigned)__cvta_generic_to_shared(smem);
    asm volatile("cp.async.cg.shared.global [%0], [%1], 16;\n" :: "r"(saddr), "l"(gmem));
}
__device__ __forceinline__ void cp_commit() {
    asm volatile("cp.async.commit_group;\n");
}
template <int N>
__device__ __forceinline__ void cp_wait() {
    asm volatile("cp.async.wait_group %0;\n" :: "n"(N));
}

// ---------------------------------------------------------------------------
// raw tf32 mma m16n8k8
// ---------------------------------------------------------------------------
__device__ __forceinline__ void mma_tf32(float* d, const unsigned* a, const unsigned* b)
{
    asm volatile(
        "mma.sync.aligned.m16n8k8.row.col.f32.tf32.tf32.f32 "
        "{%0,%1,%2,%3}, {%4,%5,%6,%7}, {%8,%9}, {%0,%1,%2,%3};\n"
        : "+f"(d[0]), "+f"(d[1]), "+f"(d[2]), "+f"(d[3])
        : "r"(a[0]), "r"(a[1]), "r"(a[2]), "r"(a[3]), "r"(b[0]), "r"(b[1]));
}
__device__ __forceinline__ unsigned f_bits(const float* p) {
    return __float_as_uint(*p);
}
__device__ __forceinline__ float tf32r(float x) { return wmma::__float_to_tf32(x); }

// ---------------------------------------------------------------------------
// Fused in-place tf32 purify of all five GEMM inputs (idempotent)
// blockIdx.y selects the tensor
// ---------------------------------------------------------------------------
__global__ void purify_all_kernel(float* __restrict__ x, float* __restrict__ wq,
                                  float* __restrict__ wk, float* __restrict__ wv,
                                  float* __restrict__ wo)
{
    float* p; int n4;
    switch (blockIdx.y) {
        case 0: p = x;  n4 = LL * DD / 4;   break;
        case 1: p = wq; n4 = DD * 2048 / 4; break;
        case 2: p = wk; n4 = DD * 512 / 4;  break;
        case 3: p = wv; n4 = DD * 512 / 4;  break;
        default: p = wo; n4 = DD * DD / 4;  break;
    }
    float4* p4 = (float4*)p;
    int i = blockIdx.x * blockDim.x + threadIdx.x;
    int stride = gridDim.x * blockDim.x;
    for (; i < n4; i += stride) {
        float4 v = p4[i];
        v.x = tf32r(v.x); v.y = tf32r(v.y); v.z = tf32r(v.z); v.w = tf32r(v.w);
        p4[i] = v;
    }
}

// ---------------------------------------------------------------------------
// tf32 GEMM v2: 128x128 tile, 128 threads (4 warps), warp tile 64x64,
// raw mma m16n8k8, double-buffered cp.async, 3 CTAs/SM.
// A smem [128][36] (m,k); B smem [32][136] (k,n). All inputs tf32-valued.
// ---------------------------------------------------------------------------
#define KC 32
#define A_LD 36
#define B_LD 136
#define GEMM_SMEM ((2 * 128 * A_LD + 2 * KC * B_LD) * 4)  // 71,680 B

template <bool ROUND_OUT>
__device__ __forceinline__ void gemm_core(
    const float* __restrict__ A, const float* __restrict__ Bp, int ldb, int cb,
    float* __restrict__ C, int ldc, int r0, int c0)
{
    extern __shared__ float sh[];
    float* As = sh;                     // [2][128*A_LD]
    float* Bs = sh + 2 * 128 * A_LD;    // [2][KC*B_LD]

    const int tid  = threadIdx.x;
    const int w    = tid >> 5;
    const int wm   = w & 1;             // 2 warps in m (64-row slabs)
    const int wn   = w >> 1;            // 2 warps in n (64-col slabs)
    const int lane = tid & 31;
    const int grp  = lane >> 2;         // 0..7
    const int tig  = lane & 3;          // 0..3

    float acc[4][8][4];                 // [mi 16-row][nj 8-col][elem]
#pragma unroll
    for (int mi = 0; mi < 4; mi++)
#pragma unroll
        for (int nj = 0; nj < 8; nj++)
#pragma unroll
            for (int e = 0; e < 4; e++) acc[mi][nj][e] = 0.f;

#define G_LOAD_STAGE(s, k0)                                                         \
    do {                                                                            \
        _Pragma("unroll") for (int it = 0; it < 8; it++) {                          \
            int lin = tid + it * 128;                                               \
            int row = lin >> 3;                                                     \
            int c4  = (lin & 7) * 4;                                                \
            cp_async16(&As[(s) * 128 * A_LD + row * A_LD + c4],                     \
                       A + (size_t)(r0 + row) * DD + (k0) + c4);                    \
        }                                                                           \
        _Pragma("unroll") for (int it = 0; it < 8; it++) {                          \
            int lin = tid + it * 128;                                               \
            int row = lin >> 5;                                                     \
            int c4  = (lin & 31) * 4;                                               \
            cp_async16(&Bs[(s) * KC * B_LD + row * B_LD + c4],                      \
                       Bp + (size_t)((k0) + row) * ldb + cb + c4);                  \
        }                                                                           \
    } while (0)

    G_LOAD_STAGE(0, 0);
    cp_commit();

    int s = 0;
    for (int k0 = 0; k0 < DD; k0 += KC, s ^= 1) {
        if (k0 + KC < DD) G_LOAD_STAGE(s ^ 1, k0 + KC);
        cp_commit();
        cp_wait<1>();
        __syncthreads();

        const float* Ab = &As[s * 128 * A_LD];
        const float* Bb = &Bs[s * KC * B_LD];
#pragma unroll
        for (int ks = 0; ks < 4; ks++) {
            unsigned a[4][4];
#pragma unroll
            for (int mi = 0; mi < 4; mi++) {
                const int ar = (wm * 64 + mi * 16 + grp) * A_LD + ks * 8 + tig;
                a[mi][0] = f_bits(&Ab[ar]);
                a[mi][1] = f_bits(&Ab[ar + 8 * A_LD]);
                a[mi][2] = f_bits(&Ab[ar + 4]);
                a[mi][3] = f_bits(&Ab[ar + 8 * A_LD + 4]);
            }
#pragma unroll
            for (int nj = 0; nj < 8; nj++) {
                const int br = (ks * 8 + tig) * B_LD + wn * 64 + nj * 8 + grp;
                unsigned b[2];
                b[0] = f_bits(&Bb[br]);
                b[1] = f_bits(&Bb[br + 4 * B_LD]);
#pragma unroll
                for (int mi = 0; mi < 4; mi++)
                    mma_tf32(acc[mi][nj], a[mi], b);
            }
        }
        __syncthreads();
    }

    // epilogue: thread owns rows (grp, grp+8), cols 2*tig..2*tig+1 per subtile
#pragma unroll
    for (int mi = 0; mi < 4; mi++) {
#pragma unroll
        for (int nj = 0; nj < 8; nj++) {
            float* acc4 = acc[mi][nj];
            if (ROUND_OUT) {
                acc4[0] = tf32r(acc4[0]); acc4[1] = tf32r(acc4[1]);
                acc4[2] = tf32r(acc4[2]); acc4[3] = tf32r(acc4[3]);
            }
            const int row = r0 + wm * 64 + mi * 16 + grp;
            const int col = c0 + wn * 64 + nj * 8 + 2 * tig;
            *(float2*)(C + (size_t)row * ldc + col)       = make_float2(acc4[0], acc4[1]);
            *(float2*)(C + (size_t)(row + 8) * ldc + col) = make_float2(acc4[2], acc4[3]);
        }
    }
#undef G_LOAD_STAGE
}

__global__ __launch_bounds__(128, 3) void gemm_qkv_kernel(
    const float* __restrict__ x, const float* __restrict__ wq,
    const float* __restrict__ wk, const float* __restrict__ wv)
{
    const int r0 = blockIdx.y * 128;
    const int c0 = blockIdx.x * 128;
    const float* Bp; int ldb; int cb;
    if (c0 < 2048)      { Bp = wq; ldb = 2048; cb = c0; }
    else if (c0 < 2560) { Bp = wk; ldb = 512;  cb = c0 - 2048; }
    else                { Bp = wv; ldb = 512;  cb = c0 - 2560; }
    gemm_core<true>(x, Bp, ldb, cb, g_qkv, QKVN, r0, c0);
}

__global__ __launch_bounds__(128, 3) void gemm_out_kernel(
    const float* __restrict__ wo, float* __restrict__ outp)
{
    gemm_core<false>(g_attn, wo, DD, blockIdx.x * 128, outp, DD,
                     blockIdx.y * 128, blockIdx.x * 128);
}

// ---------------------------------------------------------------------------
// RoPE (in-place, outputs rounded to tf32)
// ---------------------------------------------------------------------------
__global__ void rope_kernel(const float* __restrict__ fc, const float* __restrict__ fs)
{
    int idx = blockIdx.x * blockDim.x + threadIdx.x;
    const int total = LL * (NH + NKV) * (HDIM / 2);
    if (idx >= total) return;
    int i    = idx & 31;
    int rem  = idx >> 5;
    int head = rem % (NH + NKV);
    int l    = rem / (NH + NKV);
    int col  = (head < NH) ? head * HDIM + 2 * i
                           : 2048 + (head - NH) * HDIM + 2 * i;
    float* p = g_qkv + (size_t)l * QKVN + col;
    float xr = p[0], xi = p[1];
    float c = fc[l * 32 + i], s = fs[l * 32 + i];
    p[0] = tf32r(xr * c - xi * s);
    p[1] = tf32r(xr * s + xi * c);
}

// ---------------------------------------------------------------------------
// FlashAttention-2 style: raw mma.sync.m16n8k8.tf32, S and O in registers.
// 256 threads (8 warps); warp owns 16 q-rows x 64 k-cols. Q tile = 128 rows.
// (unchanged from Round 13)
// ---------------------------------------------------------------------------
#define T_LD 68
#define ATT_SMEM ((128 * T_LD + 3 * 2 * 64 * T_LD + 8 * 16 * T_LD) * 4)  // 174,080 B

__global__ __launch_bounds__(256) void attn_kernel()
{
    const int h   = blockIdx.x;
    const int qt  = (gridDim.y - 1) - blockIdx.y;   // big tiles first
    const int kvh = h >> 2;

    extern __shared__ float sm[];
    float* Qs = sm;                           // [128][T_LD] pre-scaled 1/8
    float* KV = Qs + 128 * T_LD;              // [3 stages][K|V][64][T_LD]
    float* Ps = KV + 3 * 2 * 64 * T_LD;       // [8 warps][16][T_LD]

    const int tid  = threadIdx.x;
    const int w    = tid >> 5;
    const int lane = tid & 31;
    const int grp  = lane >> 2;
    const int tig  = lane & 3;
    float* Pw = Ps + w * 16 * T_LD;

    const int rg0 = qt * 128 + w * 16 + grp;
    const int rg1 = rg0 + 8;

#define KV_STAGE(st) (KV + (st) * 2 * 64 * T_LD)
#define LOAD_KV(st, kt)                                                           \
    do {                                                                          \
        float* Kd = KV_STAGE(st);                                                 \
        float* Vd = Kd + 64 * T_LD;                                               \
        const float* base0 = g_qkv + (size_t)((kt) * 64) * QKVN;                  \
        _Pragma("unroll") for (int it = 0; it < 4; it++) {                        \
            int lin = tid + it * 256;                                             \
            int row = lin >> 4;                                                   \
            int c4  = (lin & 15) * 4;                                             \
            const float* rb = base0 + (size_t)row * QKVN;                         \
            cp_async16(&Kd[row * T_LD + c4], rb + 2048 + kvh * HDIM + c4);        \
            cp_async16(&Vd[row * T_LD + c4], rb + 2560 + kvh * HDIM + c4);        \
        }                                                                         \
    } while (0)

    LOAD_KV(0, 0);
    cp_commit();

#pragma unroll
    for (int it = 0; it < 8; it++) {
        int lin = tid + it * 256;
        int row = lin >> 4;
        int c4  = (lin & 15) * 4;
        float4 v = *(const float4*)(g_qkv + (size_t)(qt * 128 + row) * QKVN + h * HDIM + c4);
        *(float4*)(&Qs[row * T_LD + c4]) =
            make_float4(v.x * 0.125f, v.y * 0.125f, v.z * 0.125f, v.w * 0.125f);
    }

    float oacc[8][4];
#pragma unroll
    for (int n = 0; n < 8; n++)
#pragma unroll
        for (int e = 0; e < 4; e++) oacc[n][e] = 0.f;
    float m0 = -1e30f, m1 = -1e30f, l0 = 0.f, l1 = 0.f;

    const int nkt = 2 * qt + 2;
    for (int kt = 0; kt < nkt; kt++) {
        const int st = kt % 3;
        if (kt + 1 < nkt) LOAD_KV((kt + 1) % 3, kt + 1);
        cp_commit();
        cp_wait<1>();
        __syncthreads();

        const float* Kb = KV_STAGE(st);
        const float* Vb = Kb + 64 * T_LD;

        float sacc[8][4];
#pragma unroll
        for (int n = 0; n < 8; n++)
#pragma unroll
            for (int e = 0; e < 4; e++) sacc[n][e] = 0.f;

#pragma unroll
        for (int ks = 0; ks < 8; ks++) {
            const int qr0 = (w * 16 + grp) * T_LD + ks * 8 + tig;
            const int qr1 = qr0 + 8 * T_LD;
            unsigned a[4];
            a[0] = f_bits(&Qs[qr0]);
            a[1] = f_bits(&Qs[qr1]);
            a[2] = f_bits(&Qs[qr0 + 4]);
            a[3] = f_bits(&Qs[qr1 + 4]);
#pragma unroll
            for (int n = 0; n < 8; n++) {
                const int kb = (n * 8 + grp) * T_LD + ks * 8 + tig;
                unsigned b[2];
                b[0] = f_bits(&Kb[kb]);
                b[1] = f_bits(&Kb[kb + 4]);
                mma_tf32(sacc[n], a, b);
            }
        }

        {
            const int cbase = kt * 64 + 2 * tig;
            float mx0 = -1e30f, mx1 = -1e30f;
#pragma unroll
            for (int n = 0; n < 8; n++) {
                int cg = cbase + n * 8;
                if (cg     > rg0) sacc[n][0] = -1e30f;
                if (cg + 1 > rg0) sacc[n][1] = -1e30f;
                if (cg     > rg1) sacc[n][2] = -1e30f;
                if (cg + 1 > rg1) sacc[n][3] = -1e30f;
                mx0 = fmaxf(mx0, fmaxf(sacc[n][0], sacc[n][1]));
                mx1 = fmaxf(mx1, fmaxf(sacc[n][2], sacc[n][3]));
            }
            mx0 = fmaxf(mx0, __shfl_xor_sync(0xffffffffu, mx0, 1));
            mx0 = fmaxf(mx0, __shfl_xor_sync(0xffffffffu, mx0, 2));
            mx1 = fmaxf(mx1, __shfl_xor_sync(0xffffffffu, mx1, 1));
            mx1 = fmaxf(mx1, __shfl_xor_sync(0xffffffffu, mx1, 2));
            float mn0 = fmaxf(m0, mx0), mn1 = fmaxf(m1, mx1);
            float al0 = __expf(m0 - mn0), al1 = __expf(m1 - mn1);
            float ps0 = 0.f, ps1 = 0.f;
#pragma unroll
            for (int n = 0; n < 8; n++) {
                float p0 = __expf(sacc[n][0] - mn0);
                float p1 = __expf(sacc[n][1] - mn0);
                float p2 = __expf(sacc[n][2] - mn1);
                float p3 = __expf(sacc[n][3] - mn1);
                ps0 += p0 + p1; ps1 += p2 + p3;
                float2* d0 = (float2*)&Pw[grp * T_LD + n * 8 + 2 * tig];
                float2* d1 = (float2*)&Pw[(grp + 8) * T_LD + n * 8 + 2 * tig];
                *d0 = make_float2(tf32r(p0), tf32r(p1));
                *d1 = make_float2(tf32r(p2), tf32r(p3));
                oacc[n][0] *= al0; oacc[n][1] *= al0;
                oacc[n][2] *= al1; oacc[n][3] *= al1;
            }
            ps0 += __shfl_xor_sync(0xffffffffu, ps0, 1);
            ps0 += __shfl_xor_sync(0xffffffffu, ps0, 2);
            ps1 += __shfl_xor_sync(0xffffffffu, ps1, 1);
            ps1 += __shfl_xor_sync(0xffffffffu, ps1, 2);
            l0 = l0 * al0 + ps0;
            l1 = l1 * al1 + ps1;
            m0 = mn0; m1 = mn1;
        }
        __syncwarp();

#pragma unroll
        for (int kc = 0; kc < 8; kc++) {
            const int pr0 = grp * T_LD + kc * 8 + tig;
            const int pr1 = pr0 + 8 * T_LD;
            unsigned a[4];
            a[0] = f_bits(&Pw[pr0]);
            a[1] = f_bits(&Pw[pr1]);
            a[2] = f_bits(&Pw[pr0 + 4]);
            a[3] = f_bits(&Pw[pr1 + 4]);
#pragma unroll
            for (int n = 0; n < 8; n++) {
                const int vb = (kc * 8 + tig) * T_LD + n * 8 + grp;
                unsigned b[2];
                b[0] = f_bits(&Vb[vb]);
                b[1] = f_bits(&Vb[vb + 4 * T_LD]);
                mma_tf32(oacc[n], a, b);
            }
        }
    }

    {
        float inv0 = 1.f / l0, inv1 = 1.f / l1;
#pragma unroll
        for (int n = 0; n < 8; n++) {
            int col = h * HDIM + n * 8 + 2 * tig;
            float2* d0 = (float2*)&g_attn[(size_t)rg0 * DD + col];
            float2* d1 = (float2*)&g_attn[(size_t)rg1 * DD + col];
            *d0 = make_float2(tf32r(oacc[n][0] * inv0), tf32r(oacc[n][1] * inv0));
            *d1 = make_float2(tf32r(oacc[n][2] * inv1), tf32r(oacc[n][3] * inv1));
        }
    }
#undef LOAD_KV
#undef KV_STAGE
}

// ---------------------------------------------------------------------------
extern "C" void kernel_launch(void* const* d_in, const int* in_sizes, int n_in,
                              void* d_out, int out_size)
{
    float* x  = (float*)d_in[0];
    float* wq = (float*)d_in[1];
    float* wk = (float*)d_in[2];
    float* wv = (float*)d_in[3];
    float* wo = (float*)d_in[4];
    const float* fc = (const float*)d_in[5];
    const float* fs = (const float*)d_in[6];
    float* outp = (float*)d_out;

    cudaFuncSetAttribute(gemm_qkv_kernel, cudaFuncAttributeMaxDynamicSharedMemorySize, GEMM_SMEM);
    cudaFuncSetAttribute(gemm_out_kernel, cudaFuncAttributeMaxDynamicSharedMemorySize, GEMM_SMEM);
    cudaFuncSetAttribute(attn_kernel, cudaFuncAttributeMaxDynamicSharedMemorySize, ATT_SMEM);

    // Fused in-place tf32 purify (idempotent -> deterministic on replay)
    purify_all_kernel<<<dim3(256, 5), 256>>>(x, wq, wk, wv, wo);

    gemm_qkv_kernel<<<dim3(24, 16), 128, GEMM_SMEM>>>(x, wq, wk, wv);

    int total = LL * (NH + NKV) * (HDIM / 2);
    rope_kernel<<<(total + 255) / 256, 256>>>(fc, fs);

    attn_kernel<<<dim3(32, 16), 256, ATT_SMEM>>>();

    gemm_out_kernel<<<dim3(16, 16), 128, GEMM_SMEM>>>(wo, outp);
}

// round 16
// speedup vs baseline: 5.6696x; 1.7618x over previous
#include <cuda_runtime.h>
#include <cuda_fp16.h>
#include <math.h>

#define LL 2048
#define DD 2048
#define NH 32
#define NKV 8
#define HDIM 64
#define QKVN 3072

// half-precision staging buffers
__device__ __half g_xh[LL * DD];
__device__ __half g_wqt[2048 * 2048];   // [n][k]
__device__ __half g_wkt[512 * 2048];    // [n][k]
__device__ __half g_wvt[512 * 2048];    // [n][k]
__device__ __half g_wot[2048 * 2048];   // [n][k]
__device__ __half g_qkvh[LL * QKVN];    // [pos][q|k|v]
__device__ __half g_vth[NKV * HDIM * LL]; // V^T: [kvh*64+hd][pos]
__device__ __half g_attnh[LL * DD];

// ---------------------------------------------------------------------------
// cp.async helpers
// ---------------------------------------------------------------------------
__device__ __forceinline__ void cp_async16(void* smem, const void* gmem) {
    unsigned saddr = (unsigned)__cvta_generic_to_shared(smem);
    asm volatile("cp.async.cg.shared.global [%0], [%1], 16;\n" :: "r"(saddr), "l"(gmem));
}
__device__ __forceinline__ void cp_commit() {
    asm volatile("cp.async.commit_group;\n");
}
template <int N>
__device__ __forceinline__ void cp_wait() {
    asm volatile("cp.async.wait_group %0;\n" :: "n"(N));
}

// ---------------------------------------------------------------------------
// fp16 mma m16n8k16, fp32 accumulate
// ---------------------------------------------------------------------------
__device__ __forceinline__ void mma_f16(float* d, const unsigned* a, const unsigned* b)
{
    asm volatile(
        "mma.sync.aligned.m16n8k16.row.col.f32.f16.f16.f32 "
        "{%0,%1,%2,%3}, {%4,%5,%6,%7}, {%8,%9}, {%0,%1,%2,%3};\n"
        : "+f"(d[0]), "+f"(d[1]), "+f"(d[2]), "+f"(d[3])
        : "r"(a[0]), "r"(a[1]), "r"(a[2]), "r"(a[3]), "r"(b[0]), "r"(b[1]));
}
__device__ __forceinline__ unsigned h2_bits(const __half* p) {
    return *(const unsigned*)p;
}
__device__ __forceinline__ unsigned f2h2(float lo, float hi) {
    __half2 h = __floats2half2_rn(lo, hi);
    return *(unsigned*)&h;
}

// ---------------------------------------------------------------------------
// Converters (read-only from inputs; no in-place mutation)
// ---------------------------------------------------------------------------
__global__ void convx_kernel(const float* __restrict__ src, __half* __restrict__ dst, int n2)
{
    int i = blockIdx.x * blockDim.x + threadIdx.x;
    int stride = gridDim.x * blockDim.x;
    const float2* s2 = (const float2*)src;
    __half2* d2 = (__half2*)dst;
    for (; i < n2; i += stride) {
        float2 v = s2[i];
        d2[i] = __floats2half2_rn(v.x, v.y);
    }
}

// src fp32 [R][C] -> dst half [C][R]
__global__ void tconv_kernel(const float* __restrict__ src, __half* __restrict__ dst,
                             int R, int C)
{
    __shared__ float t[32][33];
    const int c0 = blockIdx.x * 32;
    const int r0 = blockIdx.y * 32;
    const int tx = threadIdx.x, ty = threadIdx.y;
#pragma unroll
    for (int j = ty; j < 32; j += 8)
        t[j][tx] = src[(size_t)(r0 + j) * C + c0 + tx];
    __syncthreads();
#pragma unroll
    for (int j = ty; j < 32; j += 8)
        dst[(size_t)(c0 + j) * R + r0 + tx] = __float2half_rn(t[tx][j]);
}

// ---------------------------------------------------------------------------
// fp16 GEMM: 128x128 tile, 128 threads (4 warps), warp tile 64x64,
// mma m16n8k16, double-buffered cp.async, 3 CTAs/SM.
// A [m][k] k-contiguous halves; B [n][k] k-contiguous halves (pre-transposed).
// ---------------------------------------------------------------------------
#define KCH 32
#define A_LDH 40
#define GEMM_SMEM ((2 * 128 * A_LDH + 2 * 128 * A_LDH) * 2)  // 40,960 B

template <bool HALF_OUT>
__device__ __forceinline__ void gemm_core(
    const __half* __restrict__ A, const __half* __restrict__ Bt,
    void* __restrict__ C, int ldc, int r0, int c0)
{
    extern __shared__ __half shh[];
    __half* As = shh;                      // [2][128*A_LDH]
    __half* Bs = shh + 2 * 128 * A_LDH;    // [2][128*A_LDH]

    const int tid  = threadIdx.x;
    const int w    = tid >> 5;
    const int wm   = w & 1;
    const int wn   = w >> 1;
    const int lane = tid & 31;
    const int grp  = lane >> 2;
    const int tig  = lane & 3;

    float acc[4][8][4];
#pragma unroll
    for (int mi = 0; mi < 4; mi++)
#pragma unroll
        for (int nj = 0; nj < 8; nj++)
#pragma unroll
            for (int e = 0; e < 4; e++) acc[mi][nj][e] = 0.f;

#define G_LOAD_STAGE(s, k0)                                                        \
    do {                                                                           \
        _Pragma("unroll") for (int it = 0; it < 4; it++) {                         \
            int lin = tid + it * 128;                                              \
            int row = lin >> 2;                                                    \
            int cc  = (lin & 3) * 8;                                               \
            cp_async16(&As[(s) * 128 * A_LDH + row * A_LDH + cc],                  \
                       A + (size_t)(r0 + row) * DD + (k0) + cc);                   \
        }                                                                          \
        _Pragma("unroll") for (int it = 0; it < 4; it++) {                         \
            int lin = tid + it * 128;                                              \
            int row = lin >> 2;                                                    \
            int cc  = (lin & 3) * 8;                                               \
            cp_async16(&Bs[(s) * 128 * A_LDH + row * A_LDH + cc],                  \
                       Bt + (size_t)row * DD + (k0) + cc);                         \
        }                                                                          \
    } while (0)

    G_LOAD_STAGE(0, 0);
    cp_commit();

    int s = 0;
    for (int k0 = 0; k0 < DD; k0 += KCH, s ^= 1) {
        if (k0 + KCH < DD) G_LOAD_STAGE(s ^ 1, k0 + KCH);
        cp_commit();
        cp_wait<1>();
        __syncthreads();

        const __half* Ab = &As[s * 128 * A_LDH];
        const __half* Bb = &Bs[s * 128 * A_LDH];
#pragma unroll
        for (int ks = 0; ks < 2; ks++) {
            unsigned a[4][4];
#pragma unroll
            for (int mi = 0; mi < 4; mi++) {
                const int ar = (wm * 64 + mi * 16 + grp) * A_LDH + ks * 16 + 2 * tig;
                a[mi][0] = h2_bits(&Ab[ar]);
                a[mi][1] = h2_bits(&Ab[ar + 8 * A_LDH]);
                a[mi][2] = h2_bits(&Ab[ar + 8]);
                a[mi][3] = h2_bits(&Ab[ar + 8 * A_LDH + 8]);
            }
#pragma unroll
            for (int nj = 0; nj < 8; nj++) {
                const int br = (wn * 64 + nj * 8 + grp) * A_LDH + ks * 16 + 2 * tig;
                unsigned b[2];
                b[0] = h2_bits(&Bb[br]);
                b[1] = h2_bits(&Bb[br + 8]);
#pragma unroll
                for (int mi = 0; mi < 4; mi++)
                    mma_f16(acc[mi][nj], a[mi], b);
            }
        }
        __syncthreads();
    }

#pragma unroll
    for (int mi = 0; mi < 4; mi++) {
#pragma unroll
        for (int nj = 0; nj < 8; nj++) {
            const float* a4 = acc[mi][nj];
            const int row = r0 + wm * 64 + mi * 16 + grp;
            const int col = c0 + wn * 64 + nj * 8 + 2 * tig;
            if (HALF_OUT) {
                __half* Ch = (__half*)C;
                *(unsigned*)&Ch[(size_t)row * ldc + col]       = f2h2(a4[0], a4[1]);
                *(unsigned*)&Ch[(size_t)(row + 8) * ldc + col] = f2h2(a4[2], a4[3]);
            } else {
                float* Cf = (float*)C;
                *(float2*)&Cf[(size_t)row * ldc + col]       = make_float2(a4[0], a4[1]);
                *(float2*)&Cf[(size_t)(row + 8) * ldc + col] = make_float2(a4[2], a4[3]);
            }
        }
    }
#undef G_LOAD_STAGE
}

__global__ __launch_bounds__(128, 3) void gemm_qkv_kernel()
{
    const int r0 = blockIdx.y * 128;
    const int c0 = blockIdx.x * 128;
    const __half* Bt; int cb;
    if (c0 < 2048)      { Bt = g_wqt; cb = c0; }
    else if (c0 < 2560) { Bt = g_wkt; cb = c0 - 2048; }
    else                { Bt = g_wvt; cb = c0 - 2560; }
    gemm_core<true>(g_xh, Bt + (size_t)cb * DD, g_qkvh, QKVN, r0, c0);
}

__global__ __launch_bounds__(128, 3) void gemm_out_kernel(float* __restrict__ outp)
{
    const int r0 = blockIdx.y * 128;
    const int c0 = blockIdx.x * 128;
    gemm_core<false>(g_attnh, g_wot + (size_t)c0 * DD, outp, DD, r0, c0);
}

// ---------------------------------------------------------------------------
// RoPE on half q/k; q additionally scaled by 1/8 (attention scale)
// ---------------------------------------------------------------------------
__global__ void rope_kernel(const float* __restrict__ fc, const float* __restrict__ fs)
{
    int idx = blockIdx.x * blockDim.x + threadIdx.x;
    const int total = LL * (NH + NKV) * (HDIM / 2);
    if (idx >= total) return;
    int i    = idx & 31;
    int rem  = idx >> 5;
    int head = rem % (NH + NKV);
    int l    = rem / (NH + NKV);
    bool isq = head < NH;
    int col  = isq ? head * HDIM + 2 * i
                   : 2048 + (head - NH) * HDIM + 2 * i;
    __half2* p = (__half2*)(g_qkvh + (size_t)l * QKVN + col);
    float2 v = __half22float2(*p);
    float c = fc[l * 32 + i], s = fs[l * 32 + i];
    float r0 = v.x * c - v.y * s;
    float r1 = v.x * s + v.y * c;
    if (isq) { r0 *= 0.125f; r1 *= 0.125f; }
    *p = __floats2half2_rn(r0, r1);
}

// ---------------------------------------------------------------------------
// V transpose: g_qkvh v part [pos][kvh*64+hd] -> g_vth [kvh*64+hd][pos]
// ---------------------------------------------------------------------------
__global__ void vt_kernel()
{
    __shared__ __half t[64][66];
    const int pt  = blockIdx.x;   // 32 pos tiles
    const int kvh = blockIdx.y;   // 8 kv heads
    const int tid = threadIdx.x;
#pragma unroll
    for (int it = 0; it < 8; it++) {
        int lin = tid + it * 256;       // 2048 half2 slots
        int row = lin >> 5;             // pos 0..63
        int c2  = (lin & 31) * 2;       // hd pair
        __half2 v = *(__half2*)(g_qkvh + (size_t)(pt * 64 + row) * QKVN
                                + 2560 + kvh * HDIM + c2);
        t[row][c2]     = __low2half(v);
        t[row][c2 + 1] = __high2half(v);
    }
    __syncthreads();
#pragma unroll
    for (int it = 0; it < 8; it++) {
        int lin = tid + it * 256;
        int row = lin >> 5;             // hd 0..63
        int c2  = (lin & 31) * 2;       // pos pair
        __half2 v = __halves2half2(t[c2][row], t[c2 + 1][row]);
        *(__half2*)(g_vth + (size_t)(kvh * HDIM + row) * LL + pt * 64 + c2) = v;
    }
}

// ---------------------------------------------------------------------------
// fp16 FlashAttention-2: Q frags in registers, P re-packed thread-locally
// (no P smem), 3-stage cp.async KV ring, 256 threads, 2 CTAs/SM.
// ---------------------------------------------------------------------------
#define T_LDH 72
#define ATT_SMEM ((128 * T_LDH + 3 * 2 * 64 * T_LDH) * 2)   // 73,728 B

__global__ __launch_bounds__(256, 2) void attn_kernel()
{
    const int h   = blockIdx.x;
    const int qt  = (gridDim.y - 1) - blockIdx.y;   // big tiles first
    const int kvh = h >> 2;

    extern __shared__ __half smh[];
    __half* Qs = smh;                         // [128][T_LDH]
    __half* KV = Qs + 128 * T_LDH;            // [3][K|V][64][T_LDH]

    const int tid  = threadIdx.x;
    const int w    = tid >> 5;
    const int lane = tid & 31;
    const int grp  = lane >> 2;
    const int tig  = lane & 3;

    const int rg0 = qt * 128 + w * 16 + grp;
    const int rg1 = rg0 + 8;

#define KV_STAGE(st) (KV + (st) * 2 * 64 * T_LDH)
#define LOAD_KV(st, kt)                                                            \
    do {                                                                           \
        __half* Kd = KV_STAGE(st);                                                 \
        __half* Vd = Kd + 64 * T_LDH;                                              \
        _Pragma("unroll") for (int it = 0; it < 2; it++) {                         \
            int lin = tid + it * 256;                                              \
            int row = lin >> 3;                                                    \
            int cc  = (lin & 7) * 8;                                               \
            cp_async16(&Kd[row * T_LDH + cc],                                      \
                       g_qkvh + (size_t)((kt) * 64 + row) * QKVN                   \
                       + 2048 + kvh * HDIM + cc);                                  \
            cp_async16(&Vd[row * T_LDH + cc],                                      \
                       g_vth + (size_t)(kvh * HDIM + row) * LL + (kt) * 64 + cc);  \
        }                                                                          \
    } while (0)

    LOAD_KV(0, 0);
    cp_commit();
    // Q tile (already scaled by 1/8 in rope)
#pragma unroll
    for (int it = 0; it < 4; it++) {
        int lin = tid + it * 256;
        int row = lin >> 3;
        int cc  = (lin & 7) * 8;
        cp_async16(&Qs[row * T_LDH + cc],
                   g_qkvh + (size_t)(qt * 128 + row) * QKVN + h * HDIM + cc);
    }
    cp_commit();

    unsigned qa[4][4];
    float oacc[8][4];
#pragma unroll
    for (int n = 0; n < 8; n++)
#pragma unroll
        for (int e = 0; e < 4; e++) oacc[n][e] = 0.f;
    float m0 = -1e30f, m1 = -1e30f, l0 = 0.f, l1 = 0.f;

    const int nkt = 2 * qt + 2;
    for (int kt = 0; kt < nkt; kt++) {
        const int st = kt % 3;
        if (kt + 1 < nkt) LOAD_KV((kt + 1) % 3, kt + 1);
        cp_commit();
        cp_wait<1>();
        __syncthreads();

        if (kt == 0) {
            // hoist Q fragments into registers (reused for all kt)
#pragma unroll
            for (int ks = 0; ks < 4; ks++) {
                const int qr = (w * 16 + grp) * T_LDH + ks * 16 + 2 * tig;
                qa[ks][0] = h2_bits(&Qs[qr]);
                qa[ks][1] = h2_bits(&Qs[qr + 8 * T_LDH]);
                qa[ks][2] = h2_bits(&Qs[qr + 8]);
                qa[ks][3] = h2_bits(&Qs[qr + 8 * T_LDH + 8]);
            }
        }

        const __half* Kb = KV_STAGE(st);
        const __half* Vb = Kb + 64 * T_LDH;

        // ---- S = Q @ K^T ----
        float sacc[8][4];
#pragma unroll
        for (int n = 0; n < 8; n++)
#pragma unroll
            for (int e = 0; e < 4; e++) sacc[n][e] = 0.f;

#pragma unroll
        for (int ks = 0; ks < 4; ks++) {
#pragma unroll
            for (int n = 0; n < 8; n++) {
                const int kb = (n * 8 + grp) * T_LDH + ks * 16 + 2 * tig;
                unsigned b[2];
                b[0] = h2_bits(&Kb[kb]);
                b[1] = h2_bits(&Kb[kb + 8]);
                mma_f16(sacc[n], qa[ks], b);
            }
        }

        // ---- softmax (registers; quad shuffles) ----
        unsigned pa[4][4];
        {
            const int cbase = kt * 64 + 2 * tig;
            float mx0 = -1e30f, mx1 = -1e30f;
#pragma unroll
            for (int n = 0; n < 8; n++) {
                int cg = cbase + n * 8;
                if (cg     > rg0) sacc[n][0] = -1e30f;
                if (cg + 1 > rg0) sacc[n][1] = -1e30f;
                if (cg     > rg1) sacc[n][2] = -1e30f;
                if (cg + 1 > rg1) sacc[n][3] = -1e30f;
                mx0 = fmaxf(mx0, fmaxf(sacc[n][0], sacc[n][1]));
                mx1 = fmaxf(mx1, fmaxf(sacc[n][2], sacc[n][3]));
            }
            mx0 = fmaxf(mx0, __shfl_xor_sync(0xffffffffu, mx0, 1));
            mx0 = fmaxf(mx0, __shfl_xor_sync(0xffffffffu, mx0, 2));
            mx1 = fmaxf(mx1, __shfl_xor_sync(0xffffffffu, mx1, 1));
            mx1 = fmaxf(mx1, __shfl_xor_sync(0xffffffffu, mx1, 2));
            float mn0 = fmaxf(m0, mx0), mn1 = fmaxf(m1, mx1);
            float al0 = __expf(m0 - mn0), al1 = __expf(m1 - mn1);
            float ps0 = 0.f, ps1 = 0.f;
#pragma unroll
            for (int n = 0; n < 8; n++) {
                float p0 = __expf(sacc[n][0] - mn0);
                float p1 = __expf(sacc[n][1] - mn0);
                float p2 = __expf(sacc[n][2] - mn1);
                float p3 = __expf(sacc[n][3] - mn1);
                ps0 += p0 + p1; ps1 += p2 + p3;
                sacc[n][0] = p0; sacc[n][1] = p1;
                sacc[n][2] = p2; sacc[n][3] = p3;
                oacc[n][0] *= al0; oacc[n][1] *= al0;
                oacc[n][2] *= al1; oacc[n][3] *= al1;
            }
            ps0 += __shfl_xor_sync(0xffffffffu, ps0, 1);
            ps0 += __shfl_xor_sync(0xffffffffu, ps0, 2);
            ps1 += __shfl_xor_sync(0xffffffffu, ps1, 1);
            ps1 += __shfl_xor_sync(0xffffffffu, ps1, 2);
            l0 = l0 * al0 + ps0;
            l1 = l1 * al1 + ps1;
            m0 = mn0; m1 = mn1;
            // re-pack P accumulators as fp16 A-fragments (thread-local!)
#pragma unroll
            for (int kc = 0; kc < 4; kc++) {
                pa[kc][0] = f2h2(sacc[2 * kc][0],     sacc[2 * kc][1]);
                pa[kc][1] = f2h2(sacc[2 * kc][2],     sacc[2 * kc][3]);
                pa[kc][2] = f2h2(sacc[2 * kc + 1][0], sacc[2 * kc + 1][1]);
                pa[kc][3] = f2h2(sacc[2 * kc + 1][2], sacc[2 * kc + 1][3]);
            }
        }

        // ---- O += P @ V  (V^T tiles: [hd][pos] k-contiguous) ----
#pragma unroll
        for (int kc = 0; kc < 4; kc++) {
#pragma unroll
            for (int n = 0; n < 8; n++) {
                const int vb = (n * 8 + grp) * T_LDH + kc * 16 + 2 * tig;
                unsigned b[2];
                b[0] = h2_bits(&Vb[vb]);
                b[1] = h2_bits(&Vb[vb + 8]);
                mma_f16(oacc[n], pa[kc], b);
            }
        }
    }

    // ---- final normalize + half write ----
    {
        float inv0 = 1.f / l0, inv1 = 1.f / l1;
#pragma unroll
        for (int n = 0; n < 8; n++) {
            int col = h * HDIM + n * 8 + 2 * tig;
            *(unsigned*)&g_attnh[(size_t)rg0 * DD + col] =
                f2h2(oacc[n][0] * inv0, oacc[n][1] * inv0);
            *(unsigned*)&g_attnh[(size_t)rg1 * DD + col] =
                f2h2(oacc[n][2] * inv1, oacc[n][3] * inv1);
        }
    }
#undef LOAD_KV
#undef KV_STAGE
}

// ---------------------------------------------------------------------------
extern "C" void kernel_launch(void* const* d_in, const int* in_sizes, int n_in,
                              void* d_out, int out_size)
{
    const float* x  = (const float*)d_in[0];
    const float* wq = (const float*)d_in[1];
    const float* wk = (const float*)d_in[2];
    const float* wv = (const float*)d_in[3];
    const float* wo = (const float*)d_in[4];
    const float* fc = (const float*)d_in[5];
    const float* fs = (const float*)d_in[6];
    float* outp = (float*)d_out;

    cudaFuncSetAttribute(attn_kernel, cudaFuncAttributeMaxDynamicSharedMemorySize, ATT_SMEM);

    __half* pxh;  cudaGetSymbolAddress((void**)&pxh,  g_xh);
    __half* pwqt; cudaGetSymbolAddress((void**)&pwqt, g_wqt);
    __half* pwkt; cudaGetSymbolAddress((void**)&pwkt, g_wkt);
    __half* pwvt; cudaGetSymbolAddress((void**)&pwvt, g_wvt);
    __half* pwot; cudaGetSymbolAddress((void**)&pwot, g_wot);

    // fp16 staging (reads inputs only; d_in never modified)
    convx_kernel<<<1024, 256>>>(x, pxh, LL * DD / 2);
    tconv_kernel<<<dim3(64, 64), dim3(32, 8)>>>(wq, pwqt, 2048, 2048);
    tconv_kernel<<<dim3(16, 64), dim3(32, 8)>>>(wk, pwkt, 2048, 512);
    tconv_kernel<<<dim3(16, 64), dim3(32, 8)>>>(wv, pwvt, 2048, 512);
    tconv_kernel<<<dim3(64, 64), dim3(32, 8)>>>(wo, pwot, 2048, 2048);

    gemm_qkv_kernel<<<dim3(24, 16), 128, GEMM_SMEM>>>();

    int total = LL * (NH + NKV) * (HDIM / 2);
    rope_kernel<<<(total + 255) / 256, 256>>>(fc, fs);
    vt_kernel<<<dim3(32, 8), 256>>>();

    attn_kernel<<<dim3(32, 16), 256, ATT_SMEM>>>();

    gemm_out_kernel<<<dim3(16, 16), 128, GEMM_SMEM>>>(outp);
}